// round 2
// baseline (speedup 1.0000x reference)
#include <cuda_runtime.h>
#include <cstdint>
#include <cstddef>

#define B_ROWS 4096
#define D_INV  1024
#define N_LAT  16384
#define TOPK   32

// ---- scratch (static __device__ arrays; no allocation allowed) ----
__device__ float g_pre[(size_t)B_ROWS * N_LAT];    // pre-activations [B, N_LAT]
__device__ float g_vals[B_ROWS * TOPK];            // raw top-k values (pre-relu)
__device__ int   g_idx [B_ROWS * TOPK];            // top-k indices
__device__ float g_decT[(size_t)N_LAT * D_INV];    // dec_w transposed [N_LAT, D_IN]

// ============================================================
// 1) Encode GEMM: pre[b,l] = sum_k x[b,k]*enc_w[l,k] + enc_b[l]
//    fp32 SIMT, 128x128 tile, BK=16, 256 threads, 8x8 microtile
// ============================================================
__global__ __launch_bounds__(256, 2)
void encode_gemm(const float* __restrict__ X, const float* __restrict__ W,
                 const float* __restrict__ bias) {
    const int BM = 128, BN = 128, BK = 16;
    __shared__ float Xs[BK][BM + 4];
    __shared__ float Ws[BK][BN + 4];

    int tid  = threadIdx.x;
    int row0 = blockIdx.y * BM;   // batch offset
    int col0 = blockIdx.x * BN;   // latent offset
    int ty = tid >> 4;            // 0..15
    int tx = tid & 15;            // 0..15

    float acc[8][8];
#pragma unroll
    for (int i = 0; i < 8; i++)
#pragma unroll
        for (int j = 0; j < 8; j++) acc[i][j] = 0.f;

    for (int k0 = 0; k0 < D_INV; k0 += BK) {
        // load X tile: 128 rows x 16 k  (512 float4, 2 per thread)
#pragma unroll
        for (int t = 0; t < 2; t++) {
            int l = tid + t * 256;
            int r = l >> 2;
            int c4 = (l & 3) * 4;
            float4 v = *(const float4*)(X + (size_t)(row0 + r) * D_INV + k0 + c4);
            Xs[c4 + 0][r] = v.x; Xs[c4 + 1][r] = v.y;
            Xs[c4 + 2][r] = v.z; Xs[c4 + 3][r] = v.w;
        }
        // load W tile: 128 latents x 16 k
#pragma unroll
        for (int t = 0; t < 2; t++) {
            int l = tid + t * 256;
            int r = l >> 2;
            int c4 = (l & 3) * 4;
            float4 v = *(const float4*)(W + (size_t)(col0 + r) * D_INV + k0 + c4);
            Ws[c4 + 0][r] = v.x; Ws[c4 + 1][r] = v.y;
            Ws[c4 + 2][r] = v.z; Ws[c4 + 3][r] = v.w;
        }
        __syncthreads();

#pragma unroll
        for (int kk = 0; kk < BK; kk++) {
            float a[8], b[8];
#pragma unroll
            for (int i = 0; i < 8; i++) a[i] = Xs[kk][ty * 8 + i];
#pragma unroll
            for (int j = 0; j < 8; j++) b[j] = Ws[kk][tx * 8 + j];
#pragma unroll
            for (int i = 0; i < 8; i++)
#pragma unroll
                for (int j = 0; j < 8; j++) acc[i][j] += a[i] * b[j];
        }
        __syncthreads();
    }

    // epilogue: add bias, store
    float bvals[8];
#pragma unroll
    for (int j = 0; j < 8; j++) bvals[j] = bias[col0 + tx * 8 + j];
#pragma unroll
    for (int i = 0; i < 8; i++) {
        int r = row0 + ty * 8 + i;
        float* p = g_pre + (size_t)r * N_LAT + col0 + tx * 8;
        float4 v0 = make_float4(acc[i][0] + bvals[0], acc[i][1] + bvals[1],
                                acc[i][2] + bvals[2], acc[i][3] + bvals[3]);
        float4 v1 = make_float4(acc[i][4] + bvals[4], acc[i][5] + bvals[5],
                                acc[i][6] + bvals[6], acc[i][7] + bvals[7]);
        *(float4*)(p + 0) = v0;
        *(float4*)(p + 4) = v1;
    }
}

// ============================================================
// 2) Exact top-32 per row, jax.lax.top_k semantics:
//    descending by value, ties broken by smaller index.
//    1 CTA (256 thr) per row; each thread owns stripe i = tid + 256*s.
//    Per extraction only the owner thread rescans its stripe.
// ============================================================
__global__ void topk_kernel() {
    extern __shared__ float sv[];   // N_LAT floats (64 KB)
    __shared__ float warp_v[8];
    __shared__ int   warp_i[8];
    __shared__ int   wi_s;

    const float NEG = -1e30f;
    int b = blockIdx.x;
    int tid = threadIdx.x;
    const float* row = g_pre + (size_t)b * N_LAT;

    // load stripe into smem + compute local argmax (fused)
    float lv = NEG; int li = 0x7fffffff;
    for (int i = tid; i < N_LAT; i += 256) {
        float v = row[i];
        sv[i] = v;
        if (v > lv || (v == lv && i < li)) { lv = v; li = i; }
    }

    for (int iter = 0; iter < TOPK; iter++) {
        // warp-level reduce (value desc, index asc)
        float v = lv; int ii = li;
#pragma unroll
        for (int o = 16; o > 0; o >>= 1) {
            float v2 = __shfl_down_sync(0xffffffffu, v, o);
            int   i2 = __shfl_down_sync(0xffffffffu, ii, o);
            if (v2 > v || (v2 == v && i2 < ii)) { v = v2; ii = i2; }
        }
        if ((tid & 31) == 0) { warp_v[tid >> 5] = v; warp_i[tid >> 5] = ii; }
        __syncthreads();
        if (tid < 32) {
            float vv; int jj;
            if (tid < 8) { vv = warp_v[tid]; jj = warp_i[tid]; }
            else         { vv = NEG;         jj = 0x7fffffff;  }
#pragma unroll
            for (int o = 4; o > 0; o >>= 1) {
                float v2 = __shfl_down_sync(0xffffffffu, vv, o);
                int   i2 = __shfl_down_sync(0xffffffffu, jj, o);
                if (v2 > vv || (v2 == vv && i2 < jj)) { vv = v2; jj = i2; }
            }
            if (tid == 0) {
                wi_s = jj;
                g_vals[b * TOPK + iter] = vv;
                g_idx [b * TOPK + iter] = jj;
            }
        }
        __syncthreads();
        int wi = wi_s;
        if ((wi & 255) == tid) {      // owner: knock out & rescan own stripe
            sv[wi] = NEG;
            lv = NEG; li = 0x7fffffff;
            for (int i = tid; i < N_LAT; i += 256) {
                float v2 = sv[i];
                if (v2 > lv || (v2 == lv && i < li)) { lv = v2; li = i; }
            }
        }
        // no extra barrier needed: wi_s is only rewritten after the next
        // iteration's __syncthreads(), which all readers must reach first.
    }
}

// ============================================================
// 3) acts region: zero fill + scatter relu(topk), idx as float
// ============================================================
__global__ void zero_kernel(float4* __restrict__ p, size_t n4) {
    size_t i = (size_t)blockIdx.x * blockDim.x + threadIdx.x;
    size_t stride = (size_t)gridDim.x * blockDim.x;
    float4 z = make_float4(0.f, 0.f, 0.f, 0.f);
    for (; i < n4; i += stride) p[i] = z;
}

__global__ void scatter_kernel(float* __restrict__ acts, float* __restrict__ idxF) {
    int t = blockIdx.x * blockDim.x + threadIdx.x;
    if (t >= B_ROWS * TOPK) return;
    int b = t / TOPK;
    int i = g_idx[t];
    if (acts) acts[(size_t)b * N_LAT + i] = fmaxf(g_vals[t], 0.f);
    if (idxF) idxF[t] = (float)i;
}

// ============================================================
// 4) transpose dec_w [D_IN, N_LAT] -> g_decT [N_LAT, D_IN]
// ============================================================
__global__ void transpose_kernel(const float* __restrict__ in) {
    __shared__ float tile[32][33];
    int bx = blockIdx.x * 32;   // latent
    int by = blockIdx.y * 32;   // d
    int tx = threadIdx.x;
    for (int yy = threadIdx.y; yy < 32; yy += 8)
        tile[yy][tx] = in[(size_t)(by + yy) * N_LAT + bx + tx];
    __syncthreads();
    for (int yy = threadIdx.y; yy < 32; yy += 8)
        g_decT[(size_t)(bx + yy) * D_INV + (by + tx)] = tile[tx][yy];
}

// ============================================================
// 5) decode: recon[b,:] = dec_b + sum_j relu(val_j) * decT[idx_j,:]
// ============================================================
__global__ __launch_bounds__(256)
void decode_kernel(const float* __restrict__ dec_b, float* __restrict__ recon) {
    __shared__ float vals[TOPK];
    __shared__ int   idxs[TOPK];
    int b = blockIdx.x, tid = threadIdx.x;
    if (tid < TOPK) {
        vals[tid] = fmaxf(g_vals[b * TOPK + tid], 0.f);
        idxs[tid] = g_idx[b * TOPK + tid];
    }
    __syncthreads();
    int d = tid * 4;
    float4 acc = *(const float4*)(dec_b + d);
#pragma unroll 8
    for (int j = 0; j < TOPK; j++) {
        const float4 w = *(const float4*)(g_decT + (size_t)idxs[j] * D_INV + d);
        float v = vals[j];
        acc.x += v * w.x; acc.y += v * w.y; acc.z += v * w.z; acc.w += v * w.w;
    }
    *(float4*)(recon + (size_t)b * D_INV + d) = acc;
}

// ============================================================
extern "C" void kernel_launch(void* const* d_in, const int* in_sizes, int n_in,
                              void* d_out, int out_size) {
    const float* x     = (const float*)d_in[0];
    const float* enc_w = (const float*)d_in[1];
    const float* enc_b = (const float*)d_in[2];
    const float* dec_w = (const float*)d_in[3];
    const float* dec_b = (const float*)d_in[4];
    float* out = (float*)d_out;

    const size_t R = (size_t)B_ROWS * D_INV;     //  4,194,304
    const size_t A = (size_t)B_ROWS * N_LAT;     // 67,108,864
    const size_t I = (size_t)B_ROWS * TOPK;      //    131,072

    // outputs concatenated in reference return order: (recon, acts, topk_idx)
    bool haveActs = ((size_t)out_size >= R + A);
    bool haveIdx  = ((size_t)out_size >= R + A + I);
    float* recon = out;
    float* acts  = haveActs ? out + R : nullptr;
    float* idxF  = haveIdx  ? out + R + A : nullptr;

    cudaFuncSetAttribute(topk_kernel, cudaFuncAttributeMaxDynamicSharedMemorySize,
                         N_LAT * (int)sizeof(float));

    dim3 gGemm(N_LAT / 128, B_ROWS / 128);
    encode_gemm<<<gGemm, 256>>>(x, enc_w, enc_b);

    topk_kernel<<<B_ROWS, 256, N_LAT * sizeof(float)>>>();

    if (haveActs) {
        size_t n4 = A / 4;
        zero_kernel<<<8192, 256>>>((float4*)acts, n4);
    }
    if (haveActs || haveIdx) {
        scatter_kernel<<<(B_ROWS * TOPK + 255) / 256, 256>>>(acts, idxF);
    }

    transpose_kernel<<<dim3(N_LAT / 32, D_INV / 32), dim3(32, 8)>>>(dec_w);
    decode_kernel<<<B_ROWS, 256>>>(dec_b, recon);
}

// round 3
// speedup vs baseline: 1.0019x; 1.0019x over previous
#include <cuda_runtime.h>
#include <cstdint>
#include <cstddef>

#define B_ROWS 4096
#define D_INV  1024
#define N_LAT  16384
#define TOPK   32

// ---- scratch (static __device__ arrays; no allocation allowed) ----
__device__ float g_pre[(size_t)B_ROWS * N_LAT];    // pre-activations [B, N_LAT]
__device__ float g_vals[B_ROWS * TOPK];            // raw top-k values (pre-relu)
__device__ int   g_idx [B_ROWS * TOPK];            // top-k indices
__device__ float g_decT[(size_t)N_LAT * D_INV];    // dec_w transposed [N_LAT, D_IN]

// ============================================================
// 1) Encode GEMM: pre[b,l] = sum_k x[b,k]*enc_w[l,k] + enc_b[l]
//    fp32 SIMT, 128x128 tile, BK=16, 256 threads, 8x8 microtile
// ============================================================
__global__ __launch_bounds__(256, 2)
void encode_gemm(const float* __restrict__ X, const float* __restrict__ W,
                 const float* __restrict__ bias) {
    const int BM = 128, BN = 128, BK = 16;
    __shared__ float Xs[BK][BM + 4];
    __shared__ float Ws[BK][BN + 4];

    int tid  = threadIdx.x;
    int row0 = blockIdx.y * BM;   // batch offset
    int col0 = blockIdx.x * BN;   // latent offset
    int ty = tid >> 4;            // 0..15
    int tx = tid & 15;            // 0..15

    float acc[8][8];
#pragma unroll
    for (int i = 0; i < 8; i++)
#pragma unroll
        for (int j = 0; j < 8; j++) acc[i][j] = 0.f;

    for (int k0 = 0; k0 < D_INV; k0 += BK) {
        // load X tile: 128 rows x 16 k  (512 float4, 2 per thread)
#pragma unroll
        for (int t = 0; t < 2; t++) {
            int l = tid + t * 256;
            int r = l >> 2;
            int c4 = (l & 3) * 4;
            float4 v = *(const float4*)(X + (size_t)(row0 + r) * D_INV + k0 + c4);
            Xs[c4 + 0][r] = v.x; Xs[c4 + 1][r] = v.y;
            Xs[c4 + 2][r] = v.z; Xs[c4 + 3][r] = v.w;
        }
        // load W tile: 128 latents x 16 k
#pragma unroll
        for (int t = 0; t < 2; t++) {
            int l = tid + t * 256;
            int r = l >> 2;
            int c4 = (l & 3) * 4;
            float4 v = *(const float4*)(W + (size_t)(col0 + r) * D_INV + k0 + c4);
            Ws[c4 + 0][r] = v.x; Ws[c4 + 1][r] = v.y;
            Ws[c4 + 2][r] = v.z; Ws[c4 + 3][r] = v.w;
        }
        __syncthreads();

#pragma unroll
        for (int kk = 0; kk < BK; kk++) {
            float a[8], b[8];
#pragma unroll
            for (int i = 0; i < 8; i++) a[i] = Xs[kk][ty * 8 + i];
#pragma unroll
            for (int j = 0; j < 8; j++) b[j] = Ws[kk][tx * 8 + j];
#pragma unroll
            for (int i = 0; i < 8; i++)
#pragma unroll
                for (int j = 0; j < 8; j++) acc[i][j] += a[i] * b[j];
        }
        __syncthreads();
    }

    // epilogue: add bias, store
    float bvals[8];
#pragma unroll
    for (int j = 0; j < 8; j++) bvals[j] = bias[col0 + tx * 8 + j];
#pragma unroll
    for (int i = 0; i < 8; i++) {
        int r = row0 + ty * 8 + i;
        float* p = g_pre + (size_t)r * N_LAT + col0 + tx * 8;
        float4 v0 = make_float4(acc[i][0] + bvals[0], acc[i][1] + bvals[1],
                                acc[i][2] + bvals[2], acc[i][3] + bvals[3]);
        float4 v1 = make_float4(acc[i][4] + bvals[4], acc[i][5] + bvals[5],
                                acc[i][6] + bvals[6], acc[i][7] + bvals[7]);
        *(float4*)(p + 0) = v0;
        *(float4*)(p + 4) = v1;
    }
}

// ============================================================
// 2) Exact top-32 per row, jax.lax.top_k semantics:
//    descending by value, ties broken by smaller index.
//    1 CTA (256 thr) per row; each thread owns stripe i = tid + 256*s.
//    Per extraction only the owner thread rescans its stripe.
// ============================================================
__global__ void topk_kernel() {
    extern __shared__ float sv[];   // N_LAT floats (64 KB)
    __shared__ float warp_v[8];
    __shared__ int   warp_i[8];
    __shared__ int   wi_s;

    const float NEG = -1e30f;
    int b = blockIdx.x;
    int tid = threadIdx.x;
    const float* row = g_pre + (size_t)b * N_LAT;

    // load stripe into smem + compute local argmax (fused)
    float lv = NEG; int li = 0x7fffffff;
    for (int i = tid; i < N_LAT; i += 256) {
        float v = row[i];
        sv[i] = v;
        if (v > lv || (v == lv && i < li)) { lv = v; li = i; }
    }

    for (int iter = 0; iter < TOPK; iter++) {
        // warp-level reduce (value desc, index asc)
        float v = lv; int ii = li;
#pragma unroll
        for (int o = 16; o > 0; o >>= 1) {
            float v2 = __shfl_down_sync(0xffffffffu, v, o);
            int   i2 = __shfl_down_sync(0xffffffffu, ii, o);
            if (v2 > v || (v2 == v && i2 < ii)) { v = v2; ii = i2; }
        }
        if ((tid & 31) == 0) { warp_v[tid >> 5] = v; warp_i[tid >> 5] = ii; }
        __syncthreads();
        if (tid < 32) {
            float vv; int jj;
            if (tid < 8) { vv = warp_v[tid]; jj = warp_i[tid]; }
            else         { vv = NEG;         jj = 0x7fffffff;  }
#pragma unroll
            for (int o = 4; o > 0; o >>= 1) {
                float v2 = __shfl_down_sync(0xffffffffu, vv, o);
                int   i2 = __shfl_down_sync(0xffffffffu, jj, o);
                if (v2 > vv || (v2 == vv && i2 < jj)) { vv = v2; jj = i2; }
            }
            if (tid == 0) {
                wi_s = jj;
                g_vals[b * TOPK + iter] = vv;
                g_idx [b * TOPK + iter] = jj;
            }
        }
        __syncthreads();
        int wi = wi_s;
        if ((wi & 255) == tid) {      // owner: knock out & rescan own stripe
            sv[wi] = NEG;
            lv = NEG; li = 0x7fffffff;
            for (int i = tid; i < N_LAT; i += 256) {
                float v2 = sv[i];
                if (v2 > lv || (v2 == lv && i < li)) { lv = v2; li = i; }
            }
        }
        // no extra barrier needed: wi_s is only rewritten after the next
        // iteration's __syncthreads(), which all readers must reach first.
    }
}

// ============================================================
// 3) acts region: zero fill + scatter relu(topk), idx as float
// ============================================================
__global__ void zero_kernel(float4* __restrict__ p, size_t n4) {
    size_t i = (size_t)blockIdx.x * blockDim.x + threadIdx.x;
    size_t stride = (size_t)gridDim.x * blockDim.x;
    float4 z = make_float4(0.f, 0.f, 0.f, 0.f);
    for (; i < n4; i += stride) p[i] = z;
}

__global__ void scatter_kernel(float* __restrict__ acts, float* __restrict__ idxF) {
    int t = blockIdx.x * blockDim.x + threadIdx.x;
    if (t >= B_ROWS * TOPK) return;
    int b = t / TOPK;
    int i = g_idx[t];
    if (acts) acts[(size_t)b * N_LAT + i] = fmaxf(g_vals[t], 0.f);
    if (idxF) idxF[t] = (float)i;
}

// ============================================================
// 4) transpose dec_w [D_IN, N_LAT] -> g_decT [N_LAT, D_IN]
// ============================================================
__global__ void transpose_kernel(const float* __restrict__ in) {
    __shared__ float tile[32][33];
    int bx = blockIdx.x * 32;   // latent
    int by = blockIdx.y * 32;   // d
    int tx = threadIdx.x;
    for (int yy = threadIdx.y; yy < 32; yy += 8)
        tile[yy][tx] = in[(size_t)(by + yy) * N_LAT + bx + tx];
    __syncthreads();
    for (int yy = threadIdx.y; yy < 32; yy += 8)
        g_decT[(size_t)(bx + yy) * D_INV + (by + tx)] = tile[tx][yy];
}

// ============================================================
// 5) decode: recon[b,:] = dec_b + sum_j relu(val_j) * decT[idx_j,:]
// ============================================================
__global__ __launch_bounds__(256)
void decode_kernel(const float* __restrict__ dec_b, float* __restrict__ recon) {
    __shared__ float vals[TOPK];
    __shared__ int   idxs[TOPK];
    int b = blockIdx.x, tid = threadIdx.x;
    if (tid < TOPK) {
        vals[tid] = fmaxf(g_vals[b * TOPK + tid], 0.f);
        idxs[tid] = g_idx[b * TOPK + tid];
    }
    __syncthreads();
    int d = tid * 4;
    float4 acc = *(const float4*)(dec_b + d);
#pragma unroll 8
    for (int j = 0; j < TOPK; j++) {
        const float4 w = *(const float4*)(g_decT + (size_t)idxs[j] * D_INV + d);
        float v = vals[j];
        acc.x += v * w.x; acc.y += v * w.y; acc.z += v * w.z; acc.w += v * w.w;
    }
    *(float4*)(recon + (size_t)b * D_INV + d) = acc;
}

// ============================================================
extern "C" void kernel_launch(void* const* d_in, const int* in_sizes, int n_in,
                              void* d_out, int out_size) {
    const float* x     = (const float*)d_in[0];
    const float* enc_w = (const float*)d_in[1];
    const float* enc_b = (const float*)d_in[2];
    const float* dec_w = (const float*)d_in[3];
    const float* dec_b = (const float*)d_in[4];
    float* out = (float*)d_out;

    const size_t R = (size_t)B_ROWS * D_INV;     //  4,194,304
    const size_t A = (size_t)B_ROWS * N_LAT;     // 67,108,864
    const size_t I = (size_t)B_ROWS * TOPK;      //    131,072

    // outputs concatenated in reference return order: (recon, acts, topk_idx)
    bool haveActs = ((size_t)out_size >= R + A);
    bool haveIdx  = ((size_t)out_size >= R + A + I);
    float* recon = out;
    float* acts  = haveActs ? out + R : nullptr;
    float* idxF  = haveIdx  ? out + R + A : nullptr;

    cudaFuncSetAttribute(topk_kernel, cudaFuncAttributeMaxDynamicSharedMemorySize,
                         N_LAT * (int)sizeof(float));

    dim3 gGemm(N_LAT / 128, B_ROWS / 128);
    encode_gemm<<<gGemm, 256>>>(x, enc_w, enc_b);

    topk_kernel<<<B_ROWS, 256, N_LAT * sizeof(float)>>>();

    if (haveActs) {
        size_t n4 = A / 4;
        zero_kernel<<<8192, 256>>>((float4*)acts, n4);
    }
    if (haveActs || haveIdx) {
        scatter_kernel<<<(B_ROWS * TOPK + 255) / 256, 256>>>(acts, idxF);
    }

    transpose_kernel<<<dim3(N_LAT / 32, D_INV / 32), dim3(32, 8)>>>(dec_w);
    decode_kernel<<<B_ROWS, 256>>>(dec_b, recon);
}